// round 1
// baseline (speedup 1.0000x reference)
#include <cuda_runtime.h>
#include <math.h>

#define CIN   256
#define COUT  128
#define BATCH 16
#define HWSZ  1024                 // 32*32
#define M_DIM (BATCH*HWSZ)         // 16384
#define K_DIM (CIN*9)              // 2304
#define N_DIM (COUT*4)             // 512

// Scratch (device globals — allocation-free per harness rules)
__device__ float g_F [K_DIM * M_DIM];   // features, K-major: F[k][m]
__device__ float g_Wk[K_DIM * N_DIM];   // rearranged weights, K-major: Wk[k][n]
__device__ float g_Z [N_DIM];           // per-(o,m,n) bias

// Cubic B-spline bases on the uniform KAN grid, matching the jnp Cox-de Boor
// recursion in float32 (same op order: sub, div, mul, add).
__device__ __forceinline__ void bspline8(float x, float* outb) {
    float t[12];
#pragma unroll
    for (int i = 0; i < 12; i++) t[i] = (float)(i - 3) * 0.4f - 1.0f;
    float b[11];
#pragma unroll
    for (int j = 0; j < 11; j++) b[j] = (x >= t[j] && x < t[j + 1]) ? 1.0f : 0.0f;
#pragma unroll
    for (int k = 1; k <= 3; k++) {
#pragma unroll
        for (int j = 0; j + k < 11; j++) {
            float left  = (x - t[j]) / (t[j + k] - t[j]) * b[j];
            float right = (t[j + k + 1] - x) / (t[j + k + 1] - t[j + 1]) * b[j + 1];
            b[j] = left + right;   // in-place safe: ascending j reads b[j+1] (old)
        }
    }
#pragma unroll
    for (int g = 0; g < 8; g++) outb[g] = b[g];
}

// Features: per (b,c,h,w) -> [silu, 8 bases] into K-major scratch.
__global__ void k_features(const float* __restrict__ x) {
    int idx = blockIdx.x * blockDim.x + threadIdx.x;
    if (idx >= BATCH * CIN * HWSZ) return;
    int hw = idx & (HWSZ - 1);
    int c  = (idx >> 10) & (CIN - 1);
    int b  = idx >> 18;
    float xv = x[((b * CIN + c) << 10) + hw];
    int m = (b << 10) + hw;
    float s = xv / (1.0f + expf(-xv));   // silu
    float bas[8];
    bspline8(xv, bas);
    g_F[(c * 9 + 0) * M_DIM + m] = s;
#pragma unroll
    for (int g = 0; g < 8; g++) g_F[(c * 9 + 1 + g) * M_DIM + m] = bas[g];
}

// Weights: K-major [k = c*9 + {0:base, 1+g:spline}][n = o*4 + mi*2 + ni], with
// the (m,n) flip folded in.
__global__ void k_weights(const float* __restrict__ base_w,
                          const float* __restrict__ spline_w) {
    int tid = blockIdx.x * blockDim.x + threadIdx.x;
    if (tid >= CIN * N_DIM) return;
    int n = tid & (N_DIM - 1);
    int c = tid >> 9;
    int o  = n >> 2;
    int mi = (n >> 1) & 1;
    int ni = n & 1;
    int fm = 1 - mi, fn = 1 - ni;
    g_Wk[(c * 9 + 0) * N_DIM + n] = base_w[((o * CIN + c) * 2 + fm) * 2 + fn];
    const float* sw = spline_w + (((o * CIN + c) * 2 + fm) * 2 + fn) * 8;
#pragma unroll
    for (int g = 0; g < 8; g++)
        g_Wk[(c * 9 + 1 + g) * N_DIM + n] = sw[g];
}

// Z[o,mi,ni] = sum_{c,g} b0[g] * sum_{(m,n) != (1-mi,1-ni)} spline_w[o,c,m,n,g]
__global__ void k_z(const float* __restrict__ spline_w) {
    int n = threadIdx.x;
    if (n >= N_DIM) return;
    int o  = n >> 2;
    int mi = (n >> 1) & 1;
    int ni = n & 1;
    int f  = (1 - mi) * 2 + (1 - ni);
    float b0[8];
    bspline8(0.0f, b0);
    float z = 0.0f;
    for (int c = 0; c < CIN; c++) {
        const float* sw = spline_w + ((o * CIN + c) * 4) * 8;
#pragma unroll
        for (int mn = 0; mn < 4; mn++) {
            if (mn == f) continue;
#pragma unroll
            for (int g = 0; g < 8; g++) z += b0[g] * sw[mn * 8 + g];
        }
    }
    g_Z[n] = z;
}

// fp32 SMEM GEMM: C[M=16384, N=512] = F^T * Wk, double-buffered,
// 128x128 block tile, 16 K-slice, 8x8 per thread. Epilogue adds Z and
// scatters to the strided ConvTranspose output layout.
__global__ void __launch_bounds__(256) k_gemm(float* __restrict__ out) {
    __shared__ float As[2][16][128];
    __shared__ float Bs[2][16][128];

    const int tid = threadIdx.x;
    const int m0  = blockIdx.y * 128;
    const int n0  = blockIdx.x * 128;
    const int tx  = tid & 15;   // n direction
    const int ty  = tid >> 4;   // m direction

    const float4* F4 = reinterpret_cast<const float4*>(g_F);
    const float4* W4 = reinterpret_cast<const float4*>(g_Wk);

    // Each tile = 16 rows x 32 float4; 256 threads x 2 float4.
    const int v1  = tid + 256;
    const int ar0 = tid >> 5, ac0 = tid & 31;
    const int ar1 = v1  >> 5, ac1 = v1  & 31;

    const int aStride = M_DIM / 4;   // 4096 float4 per k-row of F
    const int bStride = N_DIM / 4;   // 128  float4 per k-row of Wk
    const int am = m0 >> 2, bn = n0 >> 2;

    float4 pa0, pa1, pb0, pb1;
    pa0 = F4[ar0 * aStride + am + ac0];
    pa1 = F4[ar1 * aStride + am + ac1];
    pb0 = W4[ar0 * bStride + bn + ac0];
    pb1 = W4[ar1 * bStride + bn + ac1];
    ((float4*)As[0][ar0])[ac0] = pa0;
    ((float4*)As[0][ar1])[ac1] = pa1;
    ((float4*)Bs[0][ar0])[ac0] = pb0;
    ((float4*)Bs[0][ar1])[ac1] = pb1;
    __syncthreads();

    float acc[8][8];
#pragma unroll
    for (int i = 0; i < 8; i++)
#pragma unroll
        for (int j = 0; j < 8; j++) acc[i][j] = 0.0f;

    const int NK = K_DIM / 16;   // 144
    for (int kt = 0; kt < NK; kt++) {
        int cur = kt & 1;
        if (kt + 1 < NK) {
            int kb = (kt + 1) * 16;
            pa0 = F4[(kb + ar0) * aStride + am + ac0];
            pa1 = F4[(kb + ar1) * aStride + am + ac1];
            pb0 = W4[(kb + ar0) * bStride + bn + ac0];
            pb1 = W4[(kb + ar1) * bStride + bn + ac1];
        }
#pragma unroll
        for (int kk = 0; kk < 16; kk++) {
            float a[8], b[8];
            *(float4*)&a[0] = *(const float4*)&As[cur][kk][ty * 8];
            *(float4*)&a[4] = *(const float4*)&As[cur][kk][ty * 8 + 4];
            *(float4*)&b[0] = *(const float4*)&Bs[cur][kk][tx * 8];
            *(float4*)&b[4] = *(const float4*)&Bs[cur][kk][tx * 8 + 4];
#pragma unroll
            for (int i = 0; i < 8; i++)
#pragma unroll
                for (int j = 0; j < 8; j++)
                    acc[i][j] = fmaf(a[i], b[j], acc[i][j]);
        }
        if (kt + 1 < NK) {
            __syncthreads();
            int nxt = cur ^ 1;
            ((float4*)As[nxt][ar0])[ac0] = pa0;
            ((float4*)As[nxt][ar1])[ac1] = pa1;
            ((float4*)Bs[nxt][ar0])[ac0] = pb0;
            ((float4*)Bs[nxt][ar1])[ac1] = pb1;
            __syncthreads();
        }
    }

    // Epilogue: add Z, scatter to out[b, o, 2h+mi, 2w+ni]
    float zv[8];
#pragma unroll
    for (int j = 0; j < 8; j++) zv[j] = g_Z[n0 + tx * 8 + j];

#pragma unroll
    for (int i = 0; i < 8; i++) {
        int m = m0 + ty * 8 + i;
        int b = m >> 10;
        int h = (m >> 5) & 31;
        int w = m & 31;
#pragma unroll
        for (int j = 0; j < 8; j++) {
            int n  = n0 + tx * 8 + j;
            int o  = n >> 2;
            int mi = (n >> 1) & 1;
            int ni = n & 1;
            out[(((b * COUT + o) * 64) + (2 * h + mi)) * 64 + (2 * w + ni)] =
                acc[i][j] + zv[j];
        }
    }
}

extern "C" void kernel_launch(void* const* d_in, const int* in_sizes, int n_in,
                              void* d_out, int out_size) {
    const float* x        = (const float*)d_in[0];
    const float* base_w   = (const float*)d_in[1];
    const float* spline_w = (const float*)d_in[2];
    float* out = (float*)d_out;

    k_weights<<<(CIN * N_DIM + 255) / 256, 256>>>(base_w, spline_w);
    k_z<<<1, 512>>>(spline_w);
    k_features<<<(BATCH * CIN * HWSZ) / 256, 256>>>(x);
    dim3 grid(N_DIM / 128, M_DIM / 128);
    k_gemm<<<grid, 256>>>(out);
}

// round 3
// speedup vs baseline: 2.7284x; 2.7284x over previous
#include <cuda_runtime.h>
#include <cuda_bf16.h>
#include <cstdint>
#include <math.h>

#define CIN   256
#define COUT  128
#define M_DIM 16384
#define N_DIM 512
#define K_DIM 2304
#define TILE_K 32
#define NITER  (K_DIM / TILE_K)      // 72
#define NSTAGE 3

// smem stage layout: Ah | Al | Bh | Bl
#define A_STRIDE 272                 // 32 k-rows x 272B (128 m bf16 = 256B + pad)
#define A_SPLIT  (32 * A_STRIDE)     // 8704
#define B_STRIDE 80                  // 128 n-rows x 80B (32 k bf16 = 64B + pad)
#define B_SPLIT  (128 * B_STRIDE)    // 10240
#define B_BASE   (2 * A_SPLIT)       // 17408
#define STAGE_BYTES (2 * A_SPLIT + 2 * B_SPLIT)   // 37888
#define SMEM_BYTES (NSTAGE * STAGE_BYTES)         // 113664

// ---------------- device scratch ----------------
__device__ __align__(256) __nv_bfloat16 g_Fh[(size_t)K_DIM * M_DIM];  // [k][m]
__device__ __align__(256) __nv_bfloat16 g_Fl[(size_t)K_DIM * M_DIM];
__device__ __align__(256) __nv_bfloat16 g_Wh[(size_t)N_DIM * K_DIM];  // [n][k]
__device__ __align__(256) __nv_bfloat16 g_Wl[(size_t)N_DIM * K_DIM];
__device__ float g_Z[N_DIM];

// ---------------- PTX helpers ----------------
__device__ __forceinline__ uint32_t smem_u32(const void* p) {
    uint32_t a;
    asm("{ .reg .u64 t; cvta.to.shared.u64 t, %1; cvt.u32.u64 %0, t; }" : "=r"(a) : "l"(p));
    return a;
}
__device__ __forceinline__ void cp_async16(uint32_t saddr, const void* gaddr) {
    asm volatile("cp.async.cg.shared.global [%0], [%1], 16;" :: "r"(saddr), "l"(gaddr) : "memory");
}
__device__ __forceinline__ void cp_commit() {
    asm volatile("cp.async.commit_group;" ::: "memory");
}
template <int N>
__device__ __forceinline__ void cp_wait() {
    asm volatile("cp.async.wait_group %0;" :: "n"(N) : "memory");
}
__device__ __forceinline__ void ldsm_x4(uint32_t a, uint32_t* r) {
    asm volatile("ldmatrix.sync.aligned.m8n8.x4.shared.b16 {%0,%1,%2,%3}, [%4];"
        : "=r"(r[0]), "=r"(r[1]), "=r"(r[2]), "=r"(r[3]) : "r"(a));
}
__device__ __forceinline__ void ldsm_x4_t(uint32_t a, uint32_t* r) {
    asm volatile("ldmatrix.sync.aligned.m8n8.x4.trans.shared.b16 {%0,%1,%2,%3}, [%4];"
        : "=r"(r[0]), "=r"(r[1]), "=r"(r[2]), "=r"(r[3]) : "r"(a));
}
__device__ __forceinline__ void mma16816(float* c, const uint32_t* a, uint32_t b0, uint32_t b1) {
    asm volatile("mma.sync.aligned.m16n8k16.row.col.f32.bf16.bf16.f32 "
        "{%0,%1,%2,%3}, {%4,%5,%6,%7}, {%8,%9}, {%0,%1,%2,%3};"
        : "+f"(c[0]), "+f"(c[1]), "+f"(c[2]), "+f"(c[3])
        : "r"(a[0]), "r"(a[1]), "r"(a[2]), "r"(a[3]), "r"(b0), "r"(b1));
}

// ---------------- B-spline (matches jnp Cox-de Boor, fp32) ----------------
__device__ __forceinline__ void bspline8(float x, float* outb) {
    float t[12];
#pragma unroll
    for (int i = 0; i < 12; i++) t[i] = (float)(i - 3) * 0.4f - 1.0f;
    float b[11];
#pragma unroll
    for (int j = 0; j < 11; j++) b[j] = (x >= t[j] && x < t[j + 1]) ? 1.0f : 0.0f;
#pragma unroll
    for (int k = 1; k <= 3; k++) {
#pragma unroll
        for (int j = 0; j + k < 11; j++) {
            float left  = (x - t[j]) / (t[j + k] - t[j]) * b[j];
            float right = (t[j + k + 1] - x) / (t[j + k + 1] - t[j + 1]) * b[j + 1];
            b[j] = left + right;
        }
    }
#pragma unroll
    for (int g = 0; g < 8; g++) outb[g] = b[g];
}

// ---------------- features: K-major [k][m], coalesced both directions ----------------
__global__ void k_features(const float* __restrict__ x) {
    int c  = blockIdx.y;
    int m  = blockIdx.x * 256 + threadIdx.x;
    int b  = m >> 10, hw = m & 1023;
    float xv = x[((b * CIN + c) << 10) + hw];
    float f[9];
    f[0] = xv / (1.0f + expf(-xv));
    bspline8(xv, f + 1);
#pragma unroll
    for (int g = 0; g < 9; g++) {
        __nv_bfloat16 hi = __float2bfloat16(f[g]);
        __nv_bfloat16 lo = __float2bfloat16(f[g] - __bfloat162float(hi));
        size_t off = (size_t)(c * 9 + g) * M_DIM + m;
        g_Fh[off] = hi;
        g_Fl[off] = lo;
    }
}

// ---------------- weights: [n][k], flip folded ----------------
__global__ void k_weights(const float* __restrict__ base_w,
                          const float* __restrict__ spline_w) {
    int tid = blockIdx.x * blockDim.x + threadIdx.x;
    int c = tid & 255;
    int n = tid >> 8;
    int o = n >> 2, mi = (n >> 1) & 1, ni = n & 1;
    int fm = 1 - mi, fn = 1 - ni;
    float wv[9];
    wv[0] = base_w[((o * CIN + c) * 2 + fm) * 2 + fn];
    const float* sw = spline_w + (size_t)(((o * CIN + c) * 2 + fm) * 2 + fn) * 8;
#pragma unroll
    for (int g = 0; g < 8; g++) wv[1 + g] = sw[g];
    size_t base = (size_t)n * K_DIM + c * 9;
#pragma unroll
    for (int g = 0; g < 9; g++) {
        __nv_bfloat16 hi = __float2bfloat16(wv[g]);
        __nv_bfloat16 lo = __float2bfloat16(wv[g] - __bfloat162float(hi));
        g_Wh[base + g] = hi;
        g_Wl[base + g] = lo;
    }
}

// ---------------- Z bias: block per n ----------------
__global__ void k_z(const float* __restrict__ spline_w) {
    __shared__ float red[256];
    int n = blockIdx.x;
    int c = threadIdx.x;
    int o = n >> 2, mi = (n >> 1) & 1, ni = n & 1;
    int f = (1 - mi) * 2 + (1 - ni);
    float b0[8];
    bspline8(0.0f, b0);
    float z = 0.0f;
    const float* sw = spline_w + (size_t)((o * CIN + c) * 4) * 8;
#pragma unroll
    for (int mn = 0; mn < 4; mn++) {
        if (mn == f) continue;
#pragma unroll
        for (int g = 0; g < 8; g++) z += b0[g] * sw[mn * 8 + g];
    }
    red[c] = z;
    __syncthreads();
    for (int s = 128; s > 0; s >>= 1) {
        if (c < s) red[c] += red[c + s];
        __syncthreads();
    }
    if (c == 0) g_Z[n] = red[0];
}

// ---------------- stage loader: 2048 x cp.async(16B) over 256 threads ----------------
__device__ __forceinline__ void issue_loads(int it, int m0, int n0, int tid, uint32_t sb) {
    int k0 = it * TILE_K;
    uint32_t stage = sb + (it % NSTAGE) * STAGE_BYTES;
#pragma unroll
    for (int t = 0; t < 8; t++) {
        int idx = tid + t * 256;
        const __nv_bfloat16* src;
        uint32_t soff;
        if (idx < 1024) {                 // A: 2 splits x 32 k-rows x 16 chunks
            int split = idx >> 9;
            int local = idx & 511;
            int r = local >> 4, c = local & 15;
            const __nv_bfloat16* base = split ? g_Fl : g_Fh;
            src  = base + (size_t)(k0 + r) * M_DIM + m0 + c * 8;
            soff = stage + split * A_SPLIT + r * A_STRIDE + c * 16;
        } else {                          // B: 2 splits x 128 n-rows x 4 chunks
            int i2 = idx - 1024;
            int split = i2 >> 9;
            int local = i2 & 511;
            int r = local >> 2, c = local & 3;
            const __nv_bfloat16* base = split ? g_Wl : g_Wh;
            src  = base + (size_t)(n0 + r) * K_DIM + k0 + c * 8;
            soff = stage + B_BASE + split * B_SPLIT + r * B_STRIDE + c * 16;
        }
        cp_async16(soff, src);
    }
}

// ---------------- HMMA GEMM: C[16384,512] = F^T * W^T (+Z), bf16x3 ----------------
__global__ void __launch_bounds__(256, 1) k_gemm(float* __restrict__ out) {
    extern __shared__ char smem[];
    uint32_t sb = smem_u32(smem);
    const int tid  = threadIdx.x;
    const int wid  = tid >> 5, lane = tid & 31;
    const int wm   = wid >> 2;           // 0..1  (m: 64 each)
    const int wn   = wid & 3;            // 0..3  (n: 32 each)
    const int m0   = blockIdx.y * 128;
    const int n0   = blockIdx.x * 128;
    const int grp  = lane >> 3, lr = lane & 7;

    // ldmatrix lane-address offsets
    // A (trans, [k][m]): frag block (grp>>1 = k-half, grp&1 = m-half)
    const uint32_t a_off = (uint32_t)(((grp >> 1) * 8 + lr) * A_STRIDE +
                                      (grp & 1) * 16 + wm * 128);
    // B (non-trans, [n][k]): grp&1 = n-half, grp>>1 = k-chunk
    const uint32_t b_off = (uint32_t)(((grp & 1) * 8 + lr) * B_STRIDE +
                                      (grp >> 1) * 16 + wn * 32 * B_STRIDE);

    float acc[4][4][4];
#pragma unroll
    for (int i = 0; i < 4; i++)
#pragma unroll
        for (int j = 0; j < 4; j++)
#pragma unroll
            for (int v = 0; v < 4; v++) acc[i][j][v] = 0.0f;

    issue_loads(0, m0, n0, tid, sb); cp_commit();
    issue_loads(1, m0, n0, tid, sb); cp_commit();
    issue_loads(2, m0, n0, tid, sb); cp_commit();

    for (int it = 0; it < NITER; it++) {
        cp_wait<2>();
        __syncthreads();
        uint32_t st = sb + (it % NSTAGE) * STAGE_BYTES;

#pragma unroll
        for (int kk = 0; kk < 2; kk++) {
            uint32_t ah[4][4], al[4][4], bh[2][4], bl[2][4];
            uint32_t a_base = st + kk * (16 * A_STRIDE) + a_off;
            uint32_t b_base = st + B_BASE + kk * 32 + b_off;
#pragma unroll
            for (int mf = 0; mf < 4; mf++) {
                ldsm_x4_t(a_base + mf * 32, ah[mf]);
                ldsm_x4_t(a_base + A_SPLIT + mf * 32, al[mf]);
            }
#pragma unroll
            for (int u = 0; u < 2; u++) {
                ldsm_x4(b_base + u * (16 * B_STRIDE), bh[u]);
                ldsm_x4(b_base + B_SPLIT + u * (16 * B_STRIDE), bl[u]);
            }
#pragma unroll
            for (int mf = 0; mf < 4; mf++) {
#pragma unroll
                for (int nf = 0; nf < 4; nf++) {
                    int u = nf >> 1, h = nf & 1;
                    mma16816(acc[mf][nf], ah[mf], bh[u][h], bh[u][h + 2]);
                    mma16816(acc[mf][nf], ah[mf], bl[u][h], bl[u][h + 2]);
                    mma16816(acc[mf][nf], al[mf], bh[u][h], bh[u][h + 2]);
                }
            }
        }
        __syncthreads();
        int lt = it + NSTAGE;
        if (lt < NITER) issue_loads(lt, m0, n0, tid, sb);
        cp_commit();
    }

    // ---------------- epilogue: add Z, scatter to ConvTranspose layout ----------------
#pragma unroll
    for (int nf = 0; nf < 4; nf++) {
        int n  = n0 + wn * 32 + nf * 8 + (lane & 3) * 2;
        int o  = n >> 2, mi = (n >> 1) & 1;
        float z0 = g_Z[n], z1 = g_Z[n + 1];
#pragma unroll
        for (int mf = 0; mf < 4; mf++) {
#pragma unroll
            for (int half = 0; half < 2; half++) {
                int m = m0 + wm * 64 + mf * 16 + (lane >> 2) + half * 8;
                int b = m >> 10, h = (m >> 5) & 31, w = m & 31;
                float2 v;
                v.x = acc[mf][nf][half * 2 + 0] + z0;
                v.y = acc[mf][nf][half * 2 + 1] + z1;
                *(float2*)(out + ((size_t)((b * COUT + o) * 64 + 2 * h + mi)) * 64 + 2 * w) = v;
            }
        }
    }
}

extern "C" void kernel_launch(void* const* d_in, const int* in_sizes, int n_in,
                              void* d_out, int out_size) {
    const float* x        = (const float*)d_in[0];
    const float* base_w   = (const float*)d_in[1];
    const float* spline_w = (const float*)d_in[2];
    float* out = (float*)d_out;

    cudaFuncSetAttribute(k_gemm, cudaFuncAttributeMaxDynamicSharedMemorySize, SMEM_BYTES);

    k_weights<<<(N_DIM * CIN) / 256, 256>>>(base_w, spline_w);
    k_z<<<N_DIM, 256>>>(spline_w);
    dim3 fgrid(M_DIM / 256, CIN);
    k_features<<<fgrid, 256>>>(x);
    dim3 grid(N_DIM / 128, M_DIM / 128);     // (4, 128) = 512 CTAs
    k_gemm<<<grid, 256, SMEM_BYTES>>>(out);
}

// round 4
// speedup vs baseline: 2.7928x; 1.0236x over previous
#include <cuda_runtime.h>
#include <cuda_bf16.h>
#include <cstdint>
#include <math.h>

#define CIN   256
#define COUT  128
#define M_DIM 16384
#define N_DIM 512
#define K_DIM 2304
#define TILE_K 32
#define NITER  (K_DIM / TILE_K)      // 72
#define NSTAGE 2

// smem stage layout: Ah | Al | Bh | Bl
#define A_STRIDE 272                 // 32 k-rows x 272B (128 m bf16 = 256B + pad)
#define A_SPLIT  (32 * A_STRIDE)     // 8704
#define B_STRIDE 80                  // 128 n-rows x 80B (32 k bf16 = 64B + pad)
#define B_SPLIT  (128 * B_STRIDE)    // 10240
#define B_BASE   (2 * A_SPLIT)       // 17408
#define STAGE_BYTES (2 * A_SPLIT + 2 * B_SPLIT)   // 37888
#define SMEM_BYTES (NSTAGE * STAGE_BYTES)         // 75776 -> 2 CTAs/SM

// ---------------- device scratch ----------------
__device__ __align__(256) __nv_bfloat16 g_Fh[(size_t)K_DIM * M_DIM];  // [k][m]
__device__ __align__(256) __nv_bfloat16 g_Fl[(size_t)K_DIM * M_DIM];
__device__ __align__(256) __nv_bfloat16 g_Wh[(size_t)N_DIM * K_DIM];  // [n][k]
__device__ __align__(256) __nv_bfloat16 g_Wl[(size_t)N_DIM * K_DIM];
__device__ float g_Z[N_DIM];

// ---------------- PTX helpers ----------------
__device__ __forceinline__ uint32_t smem_u32(const void* p) {
    uint32_t a;
    asm("{ .reg .u64 t; cvta.to.shared.u64 t, %1; cvt.u32.u64 %0, t; }" : "=r"(a) : "l"(p));
    return a;
}
__device__ __forceinline__ void cp_async16(uint32_t saddr, const void* gaddr) {
    asm volatile("cp.async.cg.shared.global [%0], [%1], 16;" :: "r"(saddr), "l"(gaddr) : "memory");
}
__device__ __forceinline__ void cp_commit() {
    asm volatile("cp.async.commit_group;" ::: "memory");
}
template <int N>
__device__ __forceinline__ void cp_wait() {
    asm volatile("cp.async.wait_group %0;" :: "n"(N) : "memory");
}
__device__ __forceinline__ void ldsm_x4(uint32_t a, uint32_t* r) {
    asm volatile("ldmatrix.sync.aligned.m8n8.x4.shared.b16 {%0,%1,%2,%3}, [%4];"
        : "=r"(r[0]), "=r"(r[1]), "=r"(r[2]), "=r"(r[3]) : "r"(a));
}
__device__ __forceinline__ void ldsm_x4_t(uint32_t a, uint32_t* r) {
    asm volatile("ldmatrix.sync.aligned.m8n8.x4.trans.shared.b16 {%0,%1,%2,%3}, [%4];"
        : "=r"(r[0]), "=r"(r[1]), "=r"(r[2]), "=r"(r[3]) : "r"(a));
}
__device__ __forceinline__ void mma16816(float* c, const uint32_t* a, uint32_t b0, uint32_t b1) {
    asm volatile("mma.sync.aligned.m16n8k16.row.col.f32.bf16.bf16.f32 "
        "{%0,%1,%2,%3}, {%4,%5,%6,%7}, {%8,%9}, {%0,%1,%2,%3};"
        : "+f"(c[0]), "+f"(c[1]), "+f"(c[2]), "+f"(c[3])
        : "r"(a[0]), "r"(a[1]), "r"(a[2]), "r"(a[3]), "r"(b0), "r"(b1));
}

// ---------------- B-spline (matches jnp Cox-de Boor, fp32) ----------------
__device__ __forceinline__ void bspline8(float x, float* outb) {
    float t[12];
#pragma unroll
    for (int i = 0; i < 12; i++) t[i] = (float)(i - 3) * 0.4f - 1.0f;
    float b[11];
#pragma unroll
    for (int j = 0; j < 11; j++) b[j] = (x >= t[j] && x < t[j + 1]) ? 1.0f : 0.0f;
#pragma unroll
    for (int k = 1; k <= 3; k++) {
#pragma unroll
        for (int j = 0; j + k < 11; j++) {
            float left  = (x - t[j]) / (t[j + k] - t[j]) * b[j];
            float right = (t[j + k + 1] - x) / (t[j + k + 1] - t[j + 1]) * b[j + 1];
            b[j] = left + right;
        }
    }
#pragma unroll
    for (int g = 0; g < 8; g++) outb[g] = b[g];
}

// ---------------- features: K-major [k][m], coalesced both directions ----------------
__global__ void k_features(const float* __restrict__ x) {
    int c  = blockIdx.y;
    int m  = blockIdx.x * 256 + threadIdx.x;
    int b  = m >> 10, hw = m & 1023;
    float xv = x[((b * CIN + c) << 10) + hw];
    float f[9];
    f[0] = xv / (1.0f + expf(-xv));
    bspline8(xv, f + 1);
#pragma unroll
    for (int g = 0; g < 9; g++) {
        __nv_bfloat16 hi = __float2bfloat16(f[g]);
        __nv_bfloat16 lo = __float2bfloat16(f[g] - __bfloat162float(hi));
        size_t off = (size_t)(c * 9 + g) * M_DIM + m;
        g_Fh[off] = hi;
        g_Fl[off] = lo;
    }
}

// ---------------- weights: [n][k], flip folded ----------------
__global__ void k_weights(const float* __restrict__ base_w,
                          const float* __restrict__ spline_w) {
    int tid = blockIdx.x * blockDim.x + threadIdx.x;
    int c = tid & 255;
    int n = tid >> 8;
    int o = n >> 2, mi = (n >> 1) & 1, ni = n & 1;
    int fm = 1 - mi, fn = 1 - ni;
    float wv[9];
    wv[0] = base_w[((o * CIN + c) * 2 + fm) * 2 + fn];
    const float* sw = spline_w + (size_t)(((o * CIN + c) * 2 + fm) * 2 + fn) * 8;
#pragma unroll
    for (int g = 0; g < 8; g++) wv[1 + g] = sw[g];
    size_t base = (size_t)n * K_DIM + c * 9;
#pragma unroll
    for (int g = 0; g < 9; g++) {
        __nv_bfloat16 hi = __float2bfloat16(wv[g]);
        __nv_bfloat16 lo = __float2bfloat16(wv[g] - __bfloat162float(hi));
        g_Wh[base + g] = hi;
        g_Wl[base + g] = lo;
    }
}

// ---------------- Z bias: block per n ----------------
__global__ void k_z(const float* __restrict__ spline_w) {
    __shared__ float red[256];
    int n = blockIdx.x;
    int c = threadIdx.x;
    int o = n >> 2, mi = (n >> 1) & 1, ni = n & 1;
    int f = (1 - mi) * 2 + (1 - ni);
    float b0[8];
    bspline8(0.0f, b0);
    float z = 0.0f;
    const float* sw = spline_w + (size_t)((o * CIN + c) * 4) * 8;
#pragma unroll
    for (int mn = 0; mn < 4; mn++) {
        if (mn == f) continue;
#pragma unroll
        for (int g = 0; g < 8; g++) z += b0[g] * sw[mn * 8 + g];
    }
    red[c] = z;
    __syncthreads();
    for (int s = 128; s > 0; s >>= 1) {
        if (c < s) red[c] += red[c + s];
        __syncthreads();
    }
    if (c == 0) g_Z[n] = red[0];
}

// ---------------- stage loader: 2048 x cp.async(16B) over 256 threads ----------------
__device__ __forceinline__ void issue_loads(int it, int m0, int n0, int tid, uint32_t sb) {
    int k0 = it * TILE_K;
    uint32_t stage = sb + (it % NSTAGE) * STAGE_BYTES;
#pragma unroll
    for (int t = 0; t < 8; t++) {
        int idx = tid + t * 256;
        const __nv_bfloat16* src;
        uint32_t soff;
        if (idx < 1024) {                 // A: 2 splits x 32 k-rows x 16 chunks
            int split = idx >> 9;
            int local = idx & 511;
            int r = local >> 4, c = local & 15;
            const __nv_bfloat16* base = split ? g_Fl : g_Fh;
            src  = base + (size_t)(k0 + r) * M_DIM + m0 + c * 8;
            soff = stage + split * A_SPLIT + r * A_STRIDE + c * 16;
        } else {                          // B: 2 splits x 128 n-rows x 4 chunks
            int i2 = idx - 1024;
            int split = i2 >> 9;
            int local = i2 & 511;
            int r = local >> 2, c = local & 3;
            const __nv_bfloat16* base = split ? g_Wl : g_Wh;
            src  = base + (size_t)(n0 + r) * K_DIM + k0 + c * 8;
            soff = stage + B_BASE + split * B_SPLIT + r * B_STRIDE + c * 16;
        }
        cp_async16(soff, src);
    }
}

// ---------------- HMMA GEMM: C[16384,512] = F^T * W^T (+Z), bf16x3 ----------------
__global__ void __launch_bounds__(256, 2) k_gemm(float* __restrict__ out) {
    extern __shared__ char smem[];
    uint32_t sb = smem_u32(smem);
    const int tid  = threadIdx.x;
    const int wid  = tid >> 5, lane = tid & 31;
    const int wm   = wid >> 2;           // 0..1  (m: 64 each)
    const int wn   = wid & 3;            // 0..3  (n: 32 each)
    const int m0   = blockIdx.y * 128;
    const int n0   = blockIdx.x * 128;
    const int grp  = lane >> 3, lr = lane & 7;

    // ldmatrix lane-address offsets
    // A (trans, [k][m]): frag block (grp>>1 = k-half, grp&1 = m-half)
    const uint32_t a_off = (uint32_t)(((grp >> 1) * 8 + lr) * A_STRIDE +
                                      (grp & 1) * 16 + wm * 128);
    // B (non-trans, [n][k]): grp&1 = n-half, grp>>1 = k-chunk
    const uint32_t b_off = (uint32_t)(((grp & 1) * 8 + lr) * B_STRIDE +
                                      (grp >> 1) * 16 + wn * 32 * B_STRIDE);

    float acc[4][4][4];
#pragma unroll
    for (int i = 0; i < 4; i++)
#pragma unroll
        for (int j = 0; j < 4; j++)
#pragma unroll
            for (int v = 0; v < 4; v++) acc[i][j][v] = 0.0f;

    issue_loads(0, m0, n0, tid, sb); cp_commit();
    issue_loads(1, m0, n0, tid, sb); cp_commit();

    for (int it = 0; it < NITER; it++) {
        cp_wait<1>();
        __syncthreads();
        uint32_t st = sb + (it % NSTAGE) * STAGE_BYTES;

#pragma unroll
        for (int kk = 0; kk < 2; kk++) {
            uint32_t ah[4][4], al[4][4], bh[2][4], bl[2][4];
            uint32_t a_base = st + kk * (16 * A_STRIDE) + a_off;
            uint32_t b_base = st + B_BASE + kk * 32 + b_off;
#pragma unroll
            for (int mf = 0; mf < 4; mf++) {
                ldsm_x4_t(a_base + mf * 32, ah[mf]);
                ldsm_x4_t(a_base + A_SPLIT + mf * 32, al[mf]);
            }
#pragma unroll
            for (int u = 0; u < 2; u++) {
                ldsm_x4(b_base + u * (16 * B_STRIDE), bh[u]);
                ldsm_x4(b_base + B_SPLIT + u * (16 * B_STRIDE), bl[u]);
            }
#pragma unroll
            for (int mf = 0; mf < 4; mf++) {
#pragma unroll
                for (int nf = 0; nf < 4; nf++) {
                    int u = nf >> 1, h = nf & 1;
                    mma16816(acc[mf][nf], ah[mf], bh[u][h], bh[u][h + 2]);
                    mma16816(acc[mf][nf], ah[mf], bl[u][h], bl[u][h + 2]);
                    mma16816(acc[mf][nf], al[mf], bh[u][h], bh[u][h + 2]);
                }
            }
        }
        __syncthreads();
        int lt = it + NSTAGE;
        if (lt < NITER) issue_loads(lt, m0, n0, tid, sb);
        cp_commit();
    }

    // ---------------- epilogue: add Z, scatter to ConvTranspose layout ----------------
#pragma unroll
    for (int nf = 0; nf < 4; nf++) {
        int n  = n0 + wn * 32 + nf * 8 + (lane & 3) * 2;
        int o  = n >> 2, mi = (n >> 1) & 1;
        float z0 = __ldg(&g_Z[n]), z1 = __ldg(&g_Z[n + 1]);
#pragma unroll
        for (int mf = 0; mf < 4; mf++) {
#pragma unroll
            for (int half = 0; half < 2; half++) {
                int m = m0 + wm * 64 + mf * 16 + (lane >> 2) + half * 8;
                int b = m >> 10, h = (m >> 5) & 31, w = m & 31;
                float2 v;
                v.x = acc[mf][nf][half * 2 + 0] + z0;
                v.y = acc[mf][nf][half * 2 + 1] + z1;
                *(float2*)(out + ((size_t)((b * COUT + o) * 64 + 2 * h + mi)) * 64 + 2 * w) = v;
            }
        }
    }
}

extern "C" void kernel_launch(void* const* d_in, const int* in_sizes, int n_in,
                              void* d_out, int out_size) {
    const float* x        = (const float*)d_in[0];
    const float* base_w   = (const float*)d_in[1];
    const float* spline_w = (const float*)d_in[2];
    float* out = (float*)d_out;

    cudaFuncSetAttribute(k_gemm, cudaFuncAttributeMaxDynamicSharedMemorySize, SMEM_BYTES);

    k_weights<<<(N_DIM * CIN) / 256, 256>>>(base_w, spline_w);
    k_z<<<N_DIM, 256>>>(spline_w);
    dim3 fgrid(M_DIM / 256, CIN);
    k_features<<<fgrid, 256>>>(x);
    dim3 grid(N_DIM / 128, M_DIM / 128);     // (4, 128) = 512 CTAs
    k_gemm<<<grid, 256, SMEM_BYTES>>>(out);
}

// round 5
// speedup vs baseline: 3.8275x; 1.3705x over previous
#include <cuda_runtime.h>
#include <cuda_fp16.h>
#include <cstdint>
#include <math.h>

#define CIN   256
#define COUT  128
#define M_DIM 16384
#define N_DIM 512
#define K_DIM 2304
#define TILE_K 64
#define NITER  (K_DIM / TILE_K)      // 36
#define NSTAGE 2

// smem stage layout: A | Bh | Bl
#define A_STRIDE 272                 // 64 k-rows x 272B (128 m fp16 = 256B + 16 pad)
#define A_BYTES  (64 * A_STRIDE)     // 17408
#define B_STRIDE 144                 // 128 n-rows x 144B (64 k fp16 = 128B + 16 pad)
#define B_SPLIT  (128 * B_STRIDE)    // 18432
#define STAGE_BYTES (A_BYTES + 2 * B_SPLIT)       // 54272
#define SMEM_BYTES (NSTAGE * STAGE_BYTES)         // 108544

// ---------------- device scratch ----------------
__device__ __align__(256) __half g_F [(size_t)K_DIM * M_DIM];  // [k][m] features
__device__ __align__(256) __half g_Wh[(size_t)N_DIM * K_DIM];  // [n][k] weights hi
__device__ __align__(256) __half g_Wl[(size_t)N_DIM * K_DIM];  // [n][k] weights lo
__device__ float g_Z[N_DIM];

// ---------------- PTX helpers ----------------
__device__ __forceinline__ uint32_t smem_u32(const void* p) {
    uint32_t a;
    asm("{ .reg .u64 t; cvta.to.shared.u64 t, %1; cvt.u32.u64 %0, t; }" : "=r"(a) : "l"(p));
    return a;
}
__device__ __forceinline__ void cp_async16(uint32_t saddr, const void* gaddr) {
    asm volatile("cp.async.cg.shared.global [%0], [%1], 16;" :: "r"(saddr), "l"(gaddr) : "memory");
}
__device__ __forceinline__ void cp_commit() {
    asm volatile("cp.async.commit_group;" ::: "memory");
}
template <int N>
__device__ __forceinline__ void cp_wait() {
    asm volatile("cp.async.wait_group %0;" :: "n"(N) : "memory");
}
__device__ __forceinline__ void ldsm_x4(uint32_t a, uint32_t* r) {
    asm volatile("ldmatrix.sync.aligned.m8n8.x4.shared.b16 {%0,%1,%2,%3}, [%4];"
        : "=r"(r[0]), "=r"(r[1]), "=r"(r[2]), "=r"(r[3]) : "r"(a));
}
__device__ __forceinline__ void ldsm_x4_t(uint32_t a, uint32_t* r) {
    asm volatile("ldmatrix.sync.aligned.m8n8.x4.trans.shared.b16 {%0,%1,%2,%3}, [%4];"
        : "=r"(r[0]), "=r"(r[1]), "=r"(r[2]), "=r"(r[3]) : "r"(a));
}
__device__ __forceinline__ void mma16816(float* c, const uint32_t* a, uint32_t b0, uint32_t b1) {
    asm volatile("mma.sync.aligned.m16n8k16.row.col.f32.f16.f16.f32 "
        "{%0,%1,%2,%3}, {%4,%5,%6,%7}, {%8,%9}, {%0,%1,%2,%3};"
        : "+f"(c[0]), "+f"(c[1]), "+f"(c[2]), "+f"(c[3])
        : "r"(a[0]), "r"(a[1]), "r"(a[2]), "r"(a[3]), "r"(b0), "r"(b1));
}

// ---------------- B-spline (matches jnp Cox-de Boor, fp32) ----------------
__device__ __forceinline__ void bspline8(float x, float* outb) {
    float t[12];
#pragma unroll
    for (int i = 0; i < 12; i++) t[i] = (float)(i - 3) * 0.4f - 1.0f;
    float b[11];
#pragma unroll
    for (int j = 0; j < 11; j++) b[j] = (x >= t[j] && x < t[j + 1]) ? 1.0f : 0.0f;
#pragma unroll
    for (int k = 1; k <= 3; k++) {
#pragma unroll
        for (int j = 0; j + k < 11; j++) {
            float left  = (x - t[j]) / (t[j + k] - t[j]) * b[j];
            float right = (t[j + k + 1] - x) / (t[j + k + 1] - t[j + 1]) * b[j + 1];
            b[j] = left + right;
        }
    }
#pragma unroll
    for (int g = 0; g < 8; g++) outb[g] = b[g];
}

// ---------------- features: single fp16, K-major [k][m] ----------------
__global__ void k_features(const float* __restrict__ x) {
    int c  = blockIdx.y;
    int m  = blockIdx.x * 256 + threadIdx.x;
    int b  = m >> 10, hw = m & 1023;
    float xv = x[((b * CIN + c) << 10) + hw];
    float f[9];
    f[0] = xv / (1.0f + expf(-xv));
    bspline8(xv, f + 1);
#pragma unroll
    for (int g = 0; g < 9; g++)
        g_F[(size_t)(c * 9 + g) * M_DIM + m] = __float2half(f[g]);
}

// ---------------- weights: fp16 hi/lo, [n][k], flip folded ----------------
__global__ void k_weights(const float* __restrict__ base_w,
                          const float* __restrict__ spline_w) {
    int tid = blockIdx.x * blockDim.x + threadIdx.x;
    int c = tid & 255;
    int n = tid >> 8;
    int o = n >> 2, mi = (n >> 1) & 1, ni = n & 1;
    int fm = 1 - mi, fn = 1 - ni;
    float wv[9];
    wv[0] = base_w[((o * CIN + c) * 2 + fm) * 2 + fn];
    const float* sw = spline_w + (size_t)(((o * CIN + c) * 2 + fm) * 2 + fn) * 8;
#pragma unroll
    for (int g = 0; g < 8; g++) wv[1 + g] = sw[g];
    size_t base = (size_t)n * K_DIM + c * 9;
#pragma unroll
    for (int g = 0; g < 9; g++) {
        __half hi = __float2half(wv[g]);
        __half lo = __float2half(wv[g] - __half2float(hi));
        g_Wh[base + g] = hi;
        g_Wl[base + g] = lo;
    }
}

// ---------------- Z bias: block per n ----------------
__global__ void k_z(const float* __restrict__ spline_w) {
    __shared__ float red[256];
    int n = blockIdx.x;
    int c = threadIdx.x;
    int o = n >> 2, mi = (n >> 1) & 1, ni = n & 1;
    int f = (1 - mi) * 2 + (1 - ni);
    float b0[8];
    bspline8(0.0f, b0);
    float z = 0.0f;
    const float* sw = spline_w + (size_t)((o * CIN + c) * 4) * 8;
#pragma unroll
    for (int mn = 0; mn < 4; mn++) {
        if (mn == f) continue;
#pragma unroll
        for (int g = 0; g < 8; g++) z += b0[g] * sw[mn * 8 + g];
    }
    red[c] = z;
    __syncthreads();
    for (int s = 128; s > 0; s >>= 1) {
        if (c < s) red[c] += red[c + s];
        __syncthreads();
    }
    if (c == 0) g_Z[n] = red[0];
}

// ---------------- stage loader: 3072 x 16B over 256 threads ----------------
__device__ __forceinline__ void issue_loads(int it, int m0, int n0, int tid, uint32_t sb) {
    int k0 = it * TILE_K;
    uint32_t stage = sb + (it % NSTAGE) * STAGE_BYTES;
#pragma unroll
    for (int t = 0; t < 12; t++) {
        int idx = tid + t * 256;
        const __half* src;
        uint32_t soff;
        if (idx < 1024) {                 // A: 64 k-rows x 16 chunks of 16B
            int r = idx >> 4, c = idx & 15;
            src  = g_F + (size_t)(k0 + r) * M_DIM + m0 + c * 8;
            soff = stage + r * A_STRIDE + c * 16;
        } else {                          // B: 2 splits x 128 n-rows x 8 chunks
            int i2 = idx - 1024;
            int split = i2 >> 10;
            int local = i2 & 1023;
            int r = local >> 3, c = local & 7;
            const __half* base = split ? g_Wl : g_Wh;
            src  = base + (size_t)(n0 + r) * K_DIM + k0 + c * 8;
            soff = stage + A_BYTES + split * B_SPLIT + r * B_STRIDE + c * 16;
        }
        cp_async16(soff, src);
    }
}

// ---------------- HMMA GEMM: C[16384,512] = F^T * W^T (+Z), fp16 x2 ----------------
__global__ void __launch_bounds__(256, 2) k_gemm(float* __restrict__ out) {
    extern __shared__ char smem[];
    uint32_t sb = smem_u32(smem);
    const int tid  = threadIdx.x;
    const int wid  = tid >> 5, lane = tid & 31;
    const int wm   = wid >> 2;           // 0..1  (m: 64 each)
    const int wn   = wid & 3;            // 0..3  (n: 32 each)
    const int m0   = blockIdx.y * 128;
    const int n0   = blockIdx.x * 128;
    const int grp  = lane >> 3, lr = lane & 7;

    // A (trans, [k][m]): grp>>1 = k-half, grp&1 = m-half
    const uint32_t a_off = (uint32_t)(((grp >> 1) * 8 + lr) * A_STRIDE +
                                      (grp & 1) * 16 + wm * 128);
    // B (non-trans, [n][k]): grp&1 = n-half, grp>>1 = k-chunk
    const uint32_t b_off = (uint32_t)(((grp & 1) * 8 + lr) * B_STRIDE +
                                      (grp >> 1) * 16 + wn * 32 * B_STRIDE);

    float acc[4][4][4];
#pragma unroll
    for (int i = 0; i < 4; i++)
#pragma unroll
        for (int j = 0; j < 4; j++)
#pragma unroll
            for (int v = 0; v < 4; v++) acc[i][j][v] = 0.0f;

    issue_loads(0, m0, n0, tid, sb); cp_commit();
    issue_loads(1, m0, n0, tid, sb); cp_commit();

    for (int it = 0; it < NITER; it++) {
        cp_wait<1>();
        __syncthreads();
        uint32_t st = sb + (it % NSTAGE) * STAGE_BYTES;

#pragma unroll
        for (int kk = 0; kk < 4; kk++) {           // 4 x 16-k chunks
            uint32_t ah[4][4], bh[2][4], bl[2][4];
            uint32_t a_base = st + kk * (16 * A_STRIDE) + a_off;
            uint32_t b_base = st + A_BYTES + kk * 32 + b_off;
#pragma unroll
            for (int mf = 0; mf < 4; mf++)
                ldsm_x4_t(a_base + mf * 32, ah[mf]);
#pragma unroll
            for (int u = 0; u < 2; u++) {
                ldsm_x4(b_base + u * (16 * B_STRIDE), bh[u]);
                ldsm_x4(b_base + B_SPLIT + u * (16 * B_STRIDE), bl[u]);
            }
#pragma unroll
            for (int mf = 0; mf < 4; mf++) {
#pragma unroll
                for (int nf = 0; nf < 4; nf++) {
                    int u = nf >> 1, h = nf & 1;
                    mma16816(acc[mf][nf], ah[mf], bh[u][h], bh[u][h + 2]);
                    mma16816(acc[mf][nf], ah[mf], bl[u][h], bl[u][h + 2]);
                }
            }
        }
        __syncthreads();
        int lt = it + NSTAGE;
        if (lt < NITER) issue_loads(lt, m0, n0, tid, sb);
        cp_commit();
    }

    // ---------------- epilogue: add Z, scatter to ConvTranspose layout ----------------
#pragma unroll
    for (int nf = 0; nf < 4; nf++) {
        int n  = n0 + wn * 32 + nf * 8 + (lane & 3) * 2;
        int o  = n >> 2, mi = (n >> 1) & 1;
        float z0 = __ldg(&g_Z[n]), z1 = __ldg(&g_Z[n + 1]);
#pragma unroll
        for (int mf = 0; mf < 4; mf++) {
#pragma unroll
            for (int half = 0; half < 2; half++) {
                int m = m0 + wm * 64 + mf * 16 + (lane >> 2) + half * 8;
                int b = m >> 10, h = (m >> 5) & 31, w = m & 31;
                float2 v;
                v.x = acc[mf][nf][half * 2 + 0] + z0;
                v.y = acc[mf][nf][half * 2 + 1] + z1;
                *(float2*)(out + ((size_t)((b * COUT + o) * 64 + 2 * h + mi)) * 64 + 2 * w) = v;
            }
        }
    }
}

extern "C" void kernel_launch(void* const* d_in, const int* in_sizes, int n_in,
                              void* d_out, int out_size) {
    const float* x        = (const float*)d_in[0];
    const float* base_w   = (const float*)d_in[1];
    const float* spline_w = (const float*)d_in[2];
    float* out = (float*)d_out;

    cudaFuncSetAttribute(k_gemm, cudaFuncAttributeMaxDynamicSharedMemorySize, SMEM_BYTES);

    k_weights<<<(N_DIM * CIN) / 256, 256>>>(base_w, spline_w);
    k_z<<<N_DIM, 256>>>(spline_w);
    dim3 fgrid(M_DIM / 256, CIN);
    k_features<<<fgrid, 256>>>(x);
    dim3 grid(N_DIM / 128, M_DIM / 128);     // (4, 128) = 512 CTAs
    k_gemm<<<grid, 256, SMEM_BYTES>>>(out);
}

// round 6
// speedup vs baseline: 5.6689x; 1.4811x over previous
#include <cuda_runtime.h>
#include <cuda_fp16.h>
#include <cstdint>
#include <math.h>

#define CIN   256
#define COUT  128
#define M_DIM 16384
#define N_DIM 512
#define K_DIM 2304
#define TILE_K 64
#define NITER  (K_DIM / TILE_K)      // 36
#define NSTAGE 2

// smem stage layout: A | B
#define A_STRIDE 272                 // 64 k-rows x 272B (128 m fp16 = 256B + 16 pad)
#define A_BYTES  (64 * A_STRIDE)     // 17408
#define B_STRIDE 144                 // 128 n-rows x 144B (64 k fp16 = 128B + 16 pad)
#define B_BYTES  (128 * B_STRIDE)    // 18432
#define STAGE_BYTES (A_BYTES + B_BYTES)           // 35840
#define SMEM_BYTES (NSTAGE * STAGE_BYTES)         // 71680 -> 2 CTAs/SM

// ---------------- device scratch ----------------
__device__ __align__(256) __half g_F[(size_t)K_DIM * M_DIM];  // [k][m] features
__device__ __align__(256) __half g_W[(size_t)N_DIM * K_DIM];  // [n][k] weights
__device__ float g_Z[N_DIM];

// ---------------- PTX helpers ----------------
__device__ __forceinline__ uint32_t smem_u32(const void* p) {
    uint32_t a;
    asm("{ .reg .u64 t; cvta.to.shared.u64 t, %1; cvt.u32.u64 %0, t; }" : "=r"(a) : "l"(p));
    return a;
}
__device__ __forceinline__ void cp_async16(uint32_t saddr, const void* gaddr) {
    asm volatile("cp.async.cg.shared.global [%0], [%1], 16;" :: "r"(saddr), "l"(gaddr) : "memory");
}
__device__ __forceinline__ void cp_commit() {
    asm volatile("cp.async.commit_group;" ::: "memory");
}
template <int N>
__device__ __forceinline__ void cp_wait() {
    asm volatile("cp.async.wait_group %0;" :: "n"(N) : "memory");
}
__device__ __forceinline__ void ldsm_x4(uint32_t a, uint32_t* r) {
    asm volatile("ldmatrix.sync.aligned.m8n8.x4.shared.b16 {%0,%1,%2,%3}, [%4];"
        : "=r"(r[0]), "=r"(r[1]), "=r"(r[2]), "=r"(r[3]) : "r"(a));
}
__device__ __forceinline__ void ldsm_x4_t(uint32_t a, uint32_t* r) {
    asm volatile("ldmatrix.sync.aligned.m8n8.x4.trans.shared.b16 {%0,%1,%2,%3}, [%4];"
        : "=r"(r[0]), "=r"(r[1]), "=r"(r[2]), "=r"(r[3]) : "r"(a));
}
__device__ __forceinline__ void mma16816(float* c, const uint32_t* a, uint32_t b0, uint32_t b1) {
    asm volatile("mma.sync.aligned.m16n8k16.row.col.f32.f16.f16.f32 "
        "{%0,%1,%2,%3}, {%4,%5,%6,%7}, {%8,%9}, {%0,%1,%2,%3};"
        : "+f"(c[0]), "+f"(c[1]), "+f"(c[2]), "+f"(c[3])
        : "r"(a[0]), "r"(a[1]), "r"(a[2]), "r"(a[3]), "r"(b0), "r"(b1));
}

// ---------------- B-spline (matches jnp Cox-de Boor, fp32) ----------------
__device__ __forceinline__ void bspline8(float x, float* outb) {
    float t[12];
#pragma unroll
    for (int i = 0; i < 12; i++) t[i] = (float)(i - 3) * 0.4f - 1.0f;
    float b[11];
#pragma unroll
    for (int j = 0; j < 11; j++) b[j] = (x >= t[j] && x < t[j + 1]) ? 1.0f : 0.0f;
#pragma unroll
    for (int k = 1; k <= 3; k++) {
#pragma unroll
        for (int j = 0; j + k < 11; j++) {
            float left  = (x - t[j]) / (t[j + k] - t[j]) * b[j];
            float right = (t[j + k + 1] - x) / (t[j + k + 1] - t[j + 1]) * b[j + 1];
            b[j] = left + right;
        }
    }
#pragma unroll
    for (int g = 0; g < 8; g++) outb[g] = b[g];
}

// ---------------- features: single fp16, K-major [k][m] ----------------
__global__ void k_features(const float* __restrict__ x) {
    int c  = blockIdx.y;
    int m  = blockIdx.x * 256 + threadIdx.x;
    int b  = m >> 10, hw = m & 1023;
    float xv = x[((b * CIN + c) << 10) + hw];
    float f[9];
    f[0] = xv / (1.0f + expf(-xv));
    bspline8(xv, f + 1);
#pragma unroll
    for (int g = 0; g < 9; g++)
        g_F[(size_t)(c * 9 + g) * M_DIM + m] = __float2half(f[g]);
}

// ---------------- weights: single fp16, [n][k], flip folded ----------------
__global__ void k_weights(const float* __restrict__ base_w,
                          const float* __restrict__ spline_w) {
    int tid = blockIdx.x * blockDim.x + threadIdx.x;
    int c = tid & 255;
    int n = tid >> 8;
    int o = n >> 2, mi = (n >> 1) & 1, ni = n & 1;
    int fm = 1 - mi, fn = 1 - ni;
    float wv[9];
    wv[0] = base_w[((o * CIN + c) * 2 + fm) * 2 + fn];
    const float* sw = spline_w + (size_t)(((o * CIN + c) * 2 + fm) * 2 + fn) * 8;
#pragma unroll
    for (int g = 0; g < 8; g++) wv[1 + g] = sw[g];
    size_t base = (size_t)n * K_DIM + c * 9;
#pragma unroll
    for (int g = 0; g < 9; g++)
        g_W[base + g] = __float2half(wv[g]);
}

// ---------------- Z bias: block per n ----------------
__global__ void k_z(const float* __restrict__ spline_w) {
    __shared__ float red[256];
    int n = blockIdx.x;
    int c = threadIdx.x;
    int o = n >> 2, mi = (n >> 1) & 1, ni = n & 1;
    int f = (1 - mi) * 2 + (1 - ni);
    float b0[8];
    bspline8(0.0f, b0);
    float z = 0.0f;
    const float* sw = spline_w + (size_t)((o * CIN + c) * 4) * 8;
#pragma unroll
    for (int mn = 0; mn < 4; mn++) {
        if (mn == f) continue;
#pragma unroll
        for (int g = 0; g < 8; g++) z += b0[g] * sw[mn * 8 + g];
    }
    red[c] = z;
    __syncthreads();
    for (int s = 128; s > 0; s >>= 1) {
        if (c < s) red[c] += red[c + s];
        __syncthreads();
    }
    if (c == 0) g_Z[n] = red[0];
}

// ---------------- stage loader: 2048 x 16B over 256 threads ----------------
__device__ __forceinline__ void issue_loads(int it, int m0, int n0, int tid, uint32_t sb) {
    int k0 = it * TILE_K;
    uint32_t stage = sb + (it % NSTAGE) * STAGE_BYTES;
#pragma unroll
    for (int t = 0; t < 8; t++) {
        int idx = tid + t * 256;
        const __half* src;
        uint32_t soff;
        if (idx < 1024) {                 // A: 64 k-rows x 16 chunks of 16B
            int r = idx >> 4, c = idx & 15;
            src  = g_F + (size_t)(k0 + r) * M_DIM + m0 + c * 8;
            soff = stage + r * A_STRIDE + c * 16;
        } else {                          // B: 128 n-rows x 8 chunks of 16B
            int i2 = idx - 1024;
            int r = i2 >> 3, c = i2 & 7;
            src  = g_W + (size_t)(n0 + r) * K_DIM + k0 + c * 8;
            soff = stage + A_BYTES + r * B_STRIDE + c * 16;
        }
        cp_async16(soff, src);
    }
}

// ---------------- HMMA GEMM: C[16384,512] = F^T * W^T (+Z), fp16 ----------------
__global__ void __launch_bounds__(256, 2) k_gemm(float* __restrict__ out) {
    extern __shared__ char smem[];
    uint32_t sb = smem_u32(smem);
    const int tid  = threadIdx.x;
    const int wid  = tid >> 5, lane = tid & 31;
    const int wm   = wid >> 2;           // 0..1  (m: 64 each)
    const int wn   = wid & 3;            // 0..3  (n: 32 each)
    const int m0   = blockIdx.y * 128;
    const int n0   = blockIdx.x * 128;
    const int grp  = lane >> 3, lr = lane & 7;

    // A (trans, [k][m]): grp>>1 = k-half, grp&1 = m-half
    const uint32_t a_off = (uint32_t)(((grp >> 1) * 8 + lr) * A_STRIDE +
                                      (grp & 1) * 16 + wm * 128);
    // B (non-trans, [n][k]): grp&1 = n-half, grp>>1 = k-chunk
    const uint32_t b_off = (uint32_t)(((grp & 1) * 8 + lr) * B_STRIDE +
                                      (grp >> 1) * 16 + wn * 32 * B_STRIDE);

    float acc[4][4][4];
#pragma unroll
    for (int i = 0; i < 4; i++)
#pragma unroll
        for (int j = 0; j < 4; j++)
#pragma unroll
            for (int v = 0; v < 4; v++) acc[i][j][v] = 0.0f;

    issue_loads(0, m0, n0, tid, sb); cp_commit();
    issue_loads(1, m0, n0, tid, sb); cp_commit();

    for (int it = 0; it < NITER; it++) {
        cp_wait<1>();
        __syncthreads();
        uint32_t st = sb + (it % NSTAGE) * STAGE_BYTES;

#pragma unroll
        for (int kk = 0; kk < 4; kk++) {           // 4 x 16-k chunks
            uint32_t ah[4][4], bh[2][4];
            uint32_t a_base = st + kk * (16 * A_STRIDE) + a_off;
            uint32_t b_base = st + A_BYTES + kk * 32 + b_off;
#pragma unroll
            for (int mf = 0; mf < 4; mf++)
                ldsm_x4_t(a_base + mf * 32, ah[mf]);
#pragma unroll
            for (int u = 0; u < 2; u++)
                ldsm_x4(b_base + u * (16 * B_STRIDE), bh[u]);
#pragma unroll
            for (int mf = 0; mf < 4; mf++) {
#pragma unroll
                for (int nf = 0; nf < 4; nf++) {
                    int u = nf >> 1, h = nf & 1;
                    mma16816(acc[mf][nf], ah[mf], bh[u][h], bh[u][h + 2]);
                }
            }
        }
        __syncthreads();
        int lt = it + NSTAGE;
        if (lt < NITER) issue_loads(lt, m0, n0, tid, sb);
        cp_commit();
    }

    // ---------------- epilogue: add Z, scatter to ConvTranspose layout ----------------
#pragma unroll
    for (int nf = 0; nf < 4; nf++) {
        int n  = n0 + wn * 32 + nf * 8 + (lane & 3) * 2;
        int o  = n >> 2, mi = (n >> 1) & 1;
        float z0 = __ldg(&g_Z[n]), z1 = __ldg(&g_Z[n + 1]);
#pragma unroll
        for (int mf = 0; mf < 4; mf++) {
#pragma unroll
            for (int half = 0; half < 2; half++) {
                int m = m0 + wm * 64 + mf * 16 + (lane >> 2) + half * 8;
                int b = m >> 10, h = (m >> 5) & 31, w = m & 31;
                float2 v;
                v.x = acc[mf][nf][half * 2 + 0] + z0;
                v.y = acc[mf][nf][half * 2 + 1] + z1;
                *(float2*)(out + ((size_t)((b * COUT + o) * 64 + 2 * h + mi)) * 64 + 2 * w) = v;
            }
        }
    }
}

extern "C" void kernel_launch(void* const* d_in, const int* in_sizes, int n_in,
                              void* d_out, int out_size) {
    const float* x        = (const float*)d_in[0];
    const float* base_w   = (const float*)d_in[1];
    const float* spline_w = (const float*)d_in[2];
    float* out = (float*)d_out;

    cudaFuncSetAttribute(k_gemm, cudaFuncAttributeMaxDynamicSharedMemorySize, SMEM_BYTES);

    k_weights<<<(N_DIM * CIN) / 256, 256>>>(base_w, spline_w);
    k_z<<<N_DIM, 256>>>(spline_w);
    dim3 fgrid(M_DIM / 256, CIN);
    k_features<<<fgrid, 256>>>(x);
    dim3 grid(N_DIM / 128, M_DIM / 128);     // (4, 128) = 512 CTAs
    k_gemm<<<grid, 256, SMEM_BYTES>>>(out);
}

// round 7
// speedup vs baseline: 7.6492x; 1.3493x over previous
#include <cuda_runtime.h>
#include <cuda_fp16.h>
#include <cstdint>
#include <math.h>

#define CIN   256
#define COUT  128
#define M_DIM 16384
#define N_DIM 512
#define K_DIM 2304
#define TILE_K 64
#define NITER  (K_DIM / TILE_K)      // 36
#define NSTAGE 2

// smem stage layout: A | B
#define A_STRIDE 272                 // 64 k-rows x 272B (128 m fp16 = 256B + 16 pad)
#define A_BYTES  (64 * A_STRIDE)     // 17408
#define B_STRIDE 144                 // 128 n-rows x 144B (64 k fp16 = 128B + 16 pad)
#define B_BYTES  (128 * B_STRIDE)    // 18432
#define STAGE_BYTES (A_BYTES + B_BYTES)           // 35840
#define SMEM_BYTES (NSTAGE * STAGE_BYTES)         // 71680 -> 2 CTAs/SM

// ---------------- device scratch ----------------
__device__ __align__(256) __half g_F[(size_t)K_DIM * M_DIM];  // [k][m] features
__device__ __align__(256) __half g_W[(size_t)N_DIM * K_DIM];  // [n][k] weights
__device__ float g_Z[N_DIM];

// ---------------- PTX helpers ----------------
__device__ __forceinline__ uint32_t smem_u32(const void* p) {
    uint32_t a;
    asm("{ .reg .u64 t; cvta.to.shared.u64 t, %1; cvt.u32.u64 %0, t; }" : "=r"(a) : "l"(p));
    return a;
}
__device__ __forceinline__ void cp_async16(uint32_t saddr, const void* gaddr) {
    asm volatile("cp.async.cg.shared.global [%0], [%1], 16;" :: "r"(saddr), "l"(gaddr) : "memory");
}
__device__ __forceinline__ void cp_commit() {
    asm volatile("cp.async.commit_group;" ::: "memory");
}
template <int N>
__device__ __forceinline__ void cp_wait() {
    asm volatile("cp.async.wait_group %0;" :: "n"(N) : "memory");
}
__device__ __forceinline__ void ldsm_x4(uint32_t a, uint32_t* r) {
    asm volatile("ldmatrix.sync.aligned.m8n8.x4.shared.b16 {%0,%1,%2,%3}, [%4];"
        : "=r"(r[0]), "=r"(r[1]), "=r"(r[2]), "=r"(r[3]) : "r"(a));
}
__device__ __forceinline__ void ldsm_x4_t(uint32_t a, uint32_t* r) {
    asm volatile("ldmatrix.sync.aligned.m8n8.x4.trans.shared.b16 {%0,%1,%2,%3}, [%4];"
        : "=r"(r[0]), "=r"(r[1]), "=r"(r[2]), "=r"(r[3]) : "r"(a));
}
__device__ __forceinline__ void mma16816(float* c, const uint32_t* a, uint32_t b0, uint32_t b1) {
    asm volatile("mma.sync.aligned.m16n8k16.row.col.f32.f16.f16.f32 "
        "{%0,%1,%2,%3}, {%4,%5,%6,%7}, {%8,%9}, {%0,%1,%2,%3};"
        : "+f"(c[0]), "+f"(c[1]), "+f"(c[2]), "+f"(c[3])
        : "r"(a[0]), "r"(a[1]), "r"(a[2]), "r"(a[3]), "r"(b0), "r"(b1));
}

// ---------------- closed-form uniform cubic B-spline (h = 0.4) ----------------
// Nonzero bases for x in cell j = floor((x+2.2)/0.4): g = j-3..j, standard
// uniform stencil in u = (x - t_j)/h. Matches the Cox-de Boor recursion up to
// fp32 rounding (uniform knots, no repeats).
__device__ __forceinline__ void bspline8_fast(float x, float* outb) {
#pragma unroll
    for (int g = 0; g < 8; g++) outb[g] = 0.0f;
    float s = (x + 2.2f) * 2.5f;           // cell coordinate
    int j = (int)floorf(s);
    if (j < 0 || j > 10) return;            // outside knot span: all zero
    float u  = s - (float)j;
    float u2 = u * u, u3 = u2 * u;
    float om = 1.0f - u;
    float w0 = om * om * om * (1.0f / 6.0f);
    float w1 = (3.0f * u3 - 6.0f * u2 + 4.0f) * (1.0f / 6.0f);
    float w2 = (-3.0f * u3 + 3.0f * u2 + 3.0f * u + 1.0f) * (1.0f / 6.0f);
    float w3 = u3 * (1.0f / 6.0f);
    int g0 = j - 3;
    if (g0 >= 0 && g0 <= 7) outb[g0]     = w0;
    if (g0 + 1 >= 0 && g0 + 1 <= 7) outb[g0 + 1] = w1;
    if (g0 + 2 >= 0 && g0 + 2 <= 7) outb[g0 + 2] = w2;
    if (g0 + 3 >= 0 && g0 + 3 <= 7) outb[g0 + 3] = w3;
}

// exact recursion (kept for k_wz bias where it runs once per thread anyway)
__device__ __forceinline__ void bspline8(float x, float* outb) {
    float t[12];
#pragma unroll
    for (int i = 0; i < 12; i++) t[i] = (float)(i - 3) * 0.4f - 1.0f;
    float b[11];
#pragma unroll
    for (int j = 0; j < 11; j++) b[j] = (x >= t[j] && x < t[j + 1]) ? 1.0f : 0.0f;
#pragma unroll
    for (int k = 1; k <= 3; k++) {
#pragma unroll
        for (int j = 0; j + k < 11; j++) {
            float left  = (x - t[j]) / (t[j + k] - t[j]) * b[j];
            float right = (t[j + k + 1] - x) / (t[j + k + 1] - t[j + 1]) * b[j + 1];
            b[j] = left + right;
        }
    }
#pragma unroll
    for (int g = 0; g < 8; g++) outb[g] = b[g];
}

// ---------------- features: single fp16, K-major [k][m] ----------------
__global__ void k_features(const float* __restrict__ x) {
    int c  = blockIdx.y;
    int m  = blockIdx.x * 256 + threadIdx.x;
    int b  = m >> 10, hw = m & 1023;
    float xv = x[((b * CIN + c) << 10) + hw];
    float f[9];
    f[0] = xv / (1.0f + expf(-xv));
    bspline8_fast(xv, f + 1);
#pragma unroll
    for (int g = 0; g < 9; g++)
        g_F[(size_t)(c * 9 + g) * M_DIM + m] = __float2half(f[g]);
}

// ---------------- fused weights + Z: block per n ----------------
__global__ void k_wz(const float* __restrict__ base_w,
                     const float* __restrict__ spline_w) {
    __shared__ float red[256];
    int n = blockIdx.x;
    int c = threadIdx.x;
    int o = n >> 2, mi = (n >> 1) & 1, ni = n & 1;
    int fm = 1 - mi, fn = 1 - ni;
    int f  = fm * 2 + fn;

    // weights (flip folded), fp16
    float wv[9];
    wv[0] = base_w[((o * CIN + c) * 2 + fm) * 2 + fn];
    const float* sw = spline_w + (size_t)(((o * CIN + c) * 2 + fm) * 2 + fn) * 8;
#pragma unroll
    for (int g = 0; g < 8; g++) wv[1 + g] = sw[g];
    size_t base = (size_t)n * K_DIM + c * 9;
#pragma unroll
    for (int g = 0; g < 9; g++)
        g_W[base + g] = __float2half(wv[g]);

    // Z partial: sum over the 3 non-active taps
    float b0[8];
    bspline8(0.0f, b0);
    float z = 0.0f;
    const float* swa = spline_w + (size_t)((o * CIN + c) * 4) * 8;
#pragma unroll
    for (int mn = 0; mn < 4; mn++) {
        if (mn == f) continue;
#pragma unroll
        for (int g = 0; g < 8; g++) z += b0[g] * swa[mn * 8 + g];
    }
    red[c] = z;
    __syncthreads();
    for (int s = 128; s > 0; s >>= 1) {
        if (c < s) red[c] += red[c + s];
        __syncthreads();
    }
    if (c == 0) g_Z[n] = red[0];
}

// ---------------- stage loader: 2048 x 16B over 256 threads ----------------
__device__ __forceinline__ void issue_loads(int it, int m0, int n0, int tid, uint32_t sb) {
    int k0 = it * TILE_K;
    uint32_t stage = sb + (it % NSTAGE) * STAGE_BYTES;
#pragma unroll
    for (int t = 0; t < 8; t++) {
        int idx = tid + t * 256;
        const __half* src;
        uint32_t soff;
        if (idx < 1024) {                 // A: 64 k-rows x 16 chunks of 16B
            int r = idx >> 4, c = idx & 15;
            src  = g_F + (size_t)(k0 + r) * M_DIM + m0 + c * 8;
            soff = stage + r * A_STRIDE + c * 16;
        } else {                          // B: 128 n-rows x 8 chunks of 16B
            int i2 = idx - 1024;
            int r = i2 >> 3, c = i2 & 7;
            src  = g_W + (size_t)(n0 + r) * K_DIM + k0 + c * 8;
            soff = stage + A_BYTES + r * B_STRIDE + c * 16;
        }
        cp_async16(soff, src);
    }
}

// ---------------- HMMA GEMM: C[16384,512] = F^T * W^T (+Z), fp16 ----------------
__global__ void __launch_bounds__(256, 2) k_gemm(float* __restrict__ out) {
    extern __shared__ char smem[];
    uint32_t sb = smem_u32(smem);
    const int tid  = threadIdx.x;
    const int wid  = tid >> 5, lane = tid & 31;
    const int wm   = wid >> 2;           // 0..1  (m: 64 each)
    const int wn   = wid & 3;            // 0..3  (n: 32 each)
    const int m0   = blockIdx.y * 128;
    const int n0   = blockIdx.x * 128;
    const int grp  = lane >> 3, lr = lane & 7;

    // A (trans, [k][m]): grp>>1 = k-half, grp&1 = m-half
    const uint32_t a_off = (uint32_t)(((grp >> 1) * 8 + lr) * A_STRIDE +
                                      (grp & 1) * 16 + wm * 128);
    // B (non-trans, [n][k]): grp&1 = n-half, grp>>1 = k-chunk
    const uint32_t b_off = (uint32_t)(((grp & 1) * 8 + lr) * B_STRIDE +
                                      (grp >> 1) * 16 + wn * 32 * B_STRIDE);

    float acc[4][4][4];
#pragma unroll
    for (int i = 0; i < 4; i++)
#pragma unroll
        for (int j = 0; j < 4; j++)
#pragma unroll
            for (int v = 0; v < 4; v++) acc[i][j][v] = 0.0f;

    issue_loads(0, m0, n0, tid, sb); cp_commit();
    issue_loads(1, m0, n0, tid, sb); cp_commit();

    for (int it = 0; it < NITER; it++) {
        cp_wait<1>();
        __syncthreads();
        uint32_t st = sb + (it % NSTAGE) * STAGE_BYTES;

#pragma unroll
        for (int kk = 0; kk < 4; kk++) {           // 4 x 16-k chunks
            uint32_t ah[4][4], bh[2][4];
            uint32_t a_base = st + kk * (16 * A_STRIDE) + a_off;
            uint32_t b_base = st + A_BYTES + kk * 32 + b_off;
#pragma unroll
            for (int mf = 0; mf < 4; mf++)
                ldsm_x4_t(a_base + mf * 32, ah[mf]);
#pragma unroll
            for (int u = 0; u < 2; u++)
                ldsm_x4(b_base + u * (16 * B_STRIDE), bh[u]);
#pragma unroll
            for (int mf = 0; mf < 4; mf++) {
#pragma unroll
                for (int nf = 0; nf < 4; nf++) {
                    int u = nf >> 1, h = nf & 1;
                    mma16816(acc[mf][nf], ah[mf], bh[u][h], bh[u][h + 2]);
                }
            }
        }
        __syncthreads();
        int lt = it + NSTAGE;
        if (lt < NITER) issue_loads(lt, m0, n0, tid, sb);
        cp_commit();
    }

    // ---------------- epilogue: add Z, scatter to ConvTranspose layout ----------------
#pragma unroll
    for (int nf = 0; nf < 4; nf++) {
        int n  = n0 + wn * 32 + nf * 8 + (lane & 3) * 2;
        int o  = n >> 2, mi = (n >> 1) & 1;
        float z0 = __ldg(&g_Z[n]), z1 = __ldg(&g_Z[n + 1]);
#pragma unroll
        for (int mf = 0; mf < 4; mf++) {
#pragma unroll
            for (int half = 0; half < 2; half++) {
                int m = m0 + wm * 64 + mf * 16 + (lane >> 2) + half * 8;
                int b = m >> 10, h = (m >> 5) & 31, w = m & 31;
                float2 v;
                v.x = acc[mf][nf][half * 2 + 0] + z0;
                v.y = acc[mf][nf][half * 2 + 1] + z1;
                *(float2*)(out + ((size_t)((b * COUT + o) * 64 + 2 * h + mi)) * 64 + 2 * w) = v;
            }
        }
    }
}

extern "C" void kernel_launch(void* const* d_in, const int* in_sizes, int n_in,
                              void* d_out, int out_size) {
    const float* x        = (const float*)d_in[0];
    const float* base_w   = (const float*)d_in[1];
    const float* spline_w = (const float*)d_in[2];
    float* out = (float*)d_out;

    cudaFuncSetAttribute(k_gemm, cudaFuncAttributeMaxDynamicSharedMemorySize, SMEM_BYTES);

    k_wz<<<N_DIM, 256>>>(base_w, spline_w);
    dim3 fgrid(M_DIM / 256, CIN);
    k_features<<<fgrid, 256>>>(x);
    dim3 grid(N_DIM / 128, M_DIM / 128);     // (4, 128) = 512 CTAs
    k_gemm<<<grid, 256, SMEM_BYTES>>>(out);
}

// round 8
// speedup vs baseline: 7.9562x; 1.0401x over previous
#include <cuda_runtime.h>
#include <cuda_fp16.h>
#include <cstdint>
#include <math.h>

#define CIN   256
#define COUT  128
#define M_DIM 16384
#define N_DIM 512
#define K_DIM 2304
#define TILE_K 64
#define NITER  (K_DIM / TILE_K)      // 36
#define NSTAGE 2

// smem stage layout: A | B
#define A_STRIDE 272                 // 64 k-rows x 272B (128 m fp16 = 256B + 16 pad)
#define A_BYTES  (64 * A_STRIDE)     // 17408
#define B_STRIDE 144                 // 128 n-rows x 144B (64 k fp16 = 128B + 16 pad)
#define B_BYTES  (128 * B_STRIDE)    // 18432
#define STAGE_BYTES (A_BYTES + B_BYTES)           // 35840
#define SMEM_BYTES (NSTAGE * STAGE_BYTES)         // 71680 -> 2 CTAs/SM

// ---------------- device scratch ----------------
__device__ __align__(256) __half g_F[(size_t)K_DIM * M_DIM];  // [k][m] features
__device__ __align__(256) __half g_W[(size_t)N_DIM * K_DIM];  // [n][k] weights
__device__ float g_Z[N_DIM];

// ---------------- PTX helpers ----------------
__device__ __forceinline__ uint32_t smem_u32(const void* p) {
    uint32_t a;
    asm("{ .reg .u64 t; cvta.to.shared.u64 t, %1; cvt.u32.u64 %0, t; }" : "=r"(a) : "l"(p));
    return a;
}
__device__ __forceinline__ void cp_async16(uint32_t saddr, const void* gaddr) {
    asm volatile("cp.async.cg.shared.global [%0], [%1], 16;" :: "r"(saddr), "l"(gaddr) : "memory");
}
__device__ __forceinline__ void cp_commit() {
    asm volatile("cp.async.commit_group;" ::: "memory");
}
template <int N>
__device__ __forceinline__ void cp_wait() {
    asm volatile("cp.async.wait_group %0;" :: "n"(N) : "memory");
}
__device__ __forceinline__ void ldsm_x4(uint32_t a, uint32_t* r) {
    asm volatile("ldmatrix.sync.aligned.m8n8.x4.shared.b16 {%0,%1,%2,%3}, [%4];"
        : "=r"(r[0]), "=r"(r[1]), "=r"(r[2]), "=r"(r[3]) : "r"(a));
}
__device__ __forceinline__ void ldsm_x4_t(uint32_t a, uint32_t* r) {
    asm volatile("ldmatrix.sync.aligned.m8n8.x4.trans.shared.b16 {%0,%1,%2,%3}, [%4];"
        : "=r"(r[0]), "=r"(r[1]), "=r"(r[2]), "=r"(r[3]) : "r"(a));
}
__device__ __forceinline__ void mma16816(float* c, const uint32_t* a, uint32_t b0, uint32_t b1) {
    asm volatile("mma.sync.aligned.m16n8k16.row.col.f32.f16.f16.f32 "
        "{%0,%1,%2,%3}, {%4,%5,%6,%7}, {%8,%9}, {%0,%1,%2,%3};"
        : "+f"(c[0]), "+f"(c[1]), "+f"(c[2]), "+f"(c[3])
        : "r"(a[0]), "r"(a[1]), "r"(a[2]), "r"(a[3]), "r"(b0), "r"(b1));
}

// ---------------- closed-form uniform cubic B-spline (h = 0.4) ----------------
__device__ __forceinline__ void bspline8_fast(float x, float* outb) {
#pragma unroll
    for (int g = 0; g < 8; g++) outb[g] = 0.0f;
    float s = (x + 2.2f) * 2.5f;           // cell coordinate
    int j = (int)floorf(s);
    if (j < 0 || j > 10) return;            // outside knot span: all zero
    float u  = s - (float)j;
    float u2 = u * u, u3 = u2 * u;
    float om = 1.0f - u;
    float w0 = om * om * om * (1.0f / 6.0f);
    float w1 = (3.0f * u3 - 6.0f * u2 + 4.0f) * (1.0f / 6.0f);
    float w2 = (-3.0f * u3 + 3.0f * u2 + 3.0f * u + 1.0f) * (1.0f / 6.0f);
    float w3 = u3 * (1.0f / 6.0f);
    int g0 = j - 3;
    if (g0 >= 0 && g0 <= 7) outb[g0]     = w0;
    if (g0 + 1 >= 0 && g0 + 1 <= 7) outb[g0 + 1] = w1;
    if (g0 + 2 >= 0 && g0 + 2 <= 7) outb[g0 + 2] = w2;
    if (g0 + 3 >= 0 && g0 + 3 <= 7) outb[g0 + 3] = w3;
}

// exact recursion (runs once per wz thread)
__device__ __forceinline__ void bspline8(float x, float* outb) {
    float t[12];
#pragma unroll
    for (int i = 0; i < 12; i++) t[i] = (float)(i - 3) * 0.4f - 1.0f;
    float b[11];
#pragma unroll
    for (int j = 0; j < 11; j++) b[j] = (x >= t[j] && x < t[j + 1]) ? 1.0f : 0.0f;
#pragma unroll
    for (int k = 1; k <= 3; k++) {
#pragma unroll
        for (int j = 0; j + k < 11; j++) {
            float left  = (x - t[j]) / (t[j + k] - t[j]) * b[j];
            float right = (t[j + k + 1] - x) / (t[j + k + 1] - t[j + 1]) * b[j + 1];
            b[j] = left + right;
        }
    }
#pragma unroll
    for (int g = 0; g < 8; g++) outb[g] = b[g];
}

// ---------------- fused prep: features (blocks 0..16383) + weights/Z (16384..16511) ----
__global__ void k_prep(const float* __restrict__ x,
                       const float* __restrict__ base_w,
                       const float* __restrict__ spline_w) {
    __shared__ float red[4][256];
    int bid = blockIdx.x;
    int tid = threadIdx.x;

    if (bid < 16384) {
        // ------- features: single fp16, K-major [k][m] -------
        int c = bid & 255;
        int m = (bid >> 8) * 256 + tid;
        int b = m >> 10, hw = m & 1023;
        float xv = x[((b * CIN + c) << 10) + hw];
        float f[9];
        f[0] = xv / (1.0f + expf(-xv));
        bspline8_fast(xv, f + 1);
#pragma unroll
        for (int g = 0; g < 9; g++)
            g_F[(size_t)(c * 9 + g) * M_DIM + m] = __float2half(f[g]);
        return;
    }

    // ------- weights + Z: one block per output channel o -------
    int o = bid - 16384;
    int c = tid;
    float b0[8];
    bspline8(0.0f, b0);
    const float* swo = spline_w + ((size_t)(o * CIN + c)) * 32;
    float zt[4];
#pragma unroll
    for (int mn = 0; mn < 4; mn++) {         // raw storage tap (fm, fn)
        float v[8];
        *(float4*)(v)     = *(const float4*)(swo + mn * 8);
        *(float4*)(v + 4) = *(const float4*)(swo + mn * 8 + 4);
        float z = 0.0f;
#pragma unroll
        for (int g = 0; g < 8; g++) z += b0[g] * v[g];
        zt[mn] = z;
        // this raw tap is the flipped kernel value for n = (1-fm, 1-fn)
        int n = o * 4 + (1 - (mn >> 1)) * 2 + (1 - (mn & 1));
        __half* dst = g_W + (size_t)n * K_DIM + c * 9;
        dst[0] = __float2half(base_w[((o * CIN + c) * 2 + (mn >> 1)) * 2 + (mn & 1)]);
#pragma unroll
        for (int g = 0; g < 8; g++) dst[1 + g] = __float2half(v[g]);
    }
#pragma unroll
    for (int mn = 0; mn < 4; mn++) red[mn][c] = zt[mn];
    __syncthreads();
    for (int s = 128; s > 0; s >>= 1) {
        if (c < s) {
#pragma unroll
            for (int mn = 0; mn < 4; mn++) red[mn][c] += red[mn][c + s];
        }
        __syncthreads();
    }
    if (c < 4) {
        // c encodes (mi, ni); subtract the active (flipped) tap
        float total = red[0][0] + red[1][0] + red[2][0] + red[3][0];
        int f = (1 - (c >> 1)) * 2 + (1 - (c & 1));
        g_Z[o * 4 + c] = total - red[f][0];
    }
}

// ---------------- stage loader: 2048 x 16B over 256 threads ----------------
__device__ __forceinline__ void issue_loads(int it, int m0, int n0, int tid, uint32_t sb) {
    int k0 = it * TILE_K;
    uint32_t stage = sb + (it % NSTAGE) * STAGE_BYTES;
#pragma unroll
    for (int t = 0; t < 8; t++) {
        int idx = tid + t * 256;
        const __half* src;
        uint32_t soff;
        if (idx < 1024) {                 // A: 64 k-rows x 16 chunks of 16B
            int r = idx >> 4, c = idx & 15;
            src  = g_F + (size_t)(k0 + r) * M_DIM + m0 + c * 8;
            soff = stage + r * A_STRIDE + c * 16;
        } else {                          // B: 128 n-rows x 8 chunks of 16B
            int i2 = idx - 1024;
            int r = i2 >> 3, c = i2 & 7;
            src  = g_W + (size_t)(n0 + r) * K_DIM + k0 + c * 8;
            soff = stage + A_BYTES + r * B_STRIDE + c * 16;
        }
        cp_async16(soff, src);
    }
}

// ---------------- HMMA GEMM: C[16384,512] = F^T * W^T (+Z), fp16 ----------------
__global__ void __launch_bounds__(256, 2) k_gemm(float* __restrict__ out) {
    extern __shared__ char smem[];
    uint32_t sb = smem_u32(smem);
    const int tid  = threadIdx.x;
    const int wid  = tid >> 5, lane = tid & 31;
    const int wm   = wid >> 2;           // 0..1  (m: 64 each)
    const int wn   = wid & 3;            // 0..3  (n: 32 each)
    const int m0   = blockIdx.y * 128;
    const int n0   = blockIdx.x * 128;
    const int grp  = lane >> 3, lr = lane & 7;

    const uint32_t a_off = (uint32_t)(((grp >> 1) * 8 + lr) * A_STRIDE +
                                      (grp & 1) * 16 + wm * 128);
    const uint32_t b_off = (uint32_t)(((grp & 1) * 8 + lr) * B_STRIDE +
                                      (grp >> 1) * 16 + wn * 32 * B_STRIDE);

    float acc[4][4][4];
#pragma unroll
    for (int i = 0; i < 4; i++)
#pragma unroll
        for (int j = 0; j < 4; j++)
#pragma unroll
            for (int v = 0; v < 4; v++) acc[i][j][v] = 0.0f;

    issue_loads(0, m0, n0, tid, sb); cp_commit();
    issue_loads(1, m0, n0, tid, sb); cp_commit();

    for (int it = 0; it < NITER; it++) {
        cp_wait<1>();
        __syncthreads();
        uint32_t st = sb + (it % NSTAGE) * STAGE_BYTES;

#pragma unroll
        for (int kk = 0; kk < 4; kk++) {           // 4 x 16-k chunks
            uint32_t ah[4][4], bh[2][4];
            uint32_t a_base = st + kk * (16 * A_STRIDE) + a_off;
            uint32_t b_base = st + A_BYTES + kk * 32 + b_off;
#pragma unroll
            for (int mf = 0; mf < 4; mf++)
                ldsm_x4_t(a_base + mf * 32, ah[mf]);
#pragma unroll
            for (int u = 0; u < 2; u++)
                ldsm_x4(b_base + u * (16 * B_STRIDE), bh[u]);
#pragma unroll
            for (int mf = 0; mf < 4; mf++) {
#pragma unroll
                for (int nf = 0; nf < 4; nf++) {
                    int u = nf >> 1, h = nf & 1;
                    mma16816(acc[mf][nf], ah[mf], bh[u][h], bh[u][h + 2]);
                }
            }
        }
        __syncthreads();
        int lt = it + NSTAGE;
        if (lt < NITER) issue_loads(lt, m0, n0, tid, sb);
        cp_commit();
    }

    // ---------------- epilogue: add Z, scatter to ConvTranspose layout ----------------
#pragma unroll
    for (int nf = 0; nf < 4; nf++) {
        int n  = n0 + wn * 32 + nf * 8 + (lane & 3) * 2;
        int o  = n >> 2, mi = (n >> 1) & 1;
        float z0 = __ldg(&g_Z[n]), z1 = __ldg(&g_Z[n + 1]);
#pragma unroll
        for (int mf = 0; mf < 4; mf++) {
#pragma unroll
            for (int half = 0; half < 2; half++) {
                int m = m0 + wm * 64 + mf * 16 + (lane >> 2) + half * 8;
                int b = m >> 10, h = (m >> 5) & 31, w = m & 31;
                float2 v;
                v.x = acc[mf][nf][half * 2 + 0] + z0;
                v.y = acc[mf][nf][half * 2 + 1] + z1;
                *(float2*)(out + ((size_t)((b * COUT + o) * 64 + 2 * h + mi)) * 64 + 2 * w) = v;
            }
        }
    }
}

extern "C" void kernel_launch(void* const* d_in, const int* in_sizes, int n_in,
                              void* d_out, int out_size) {
    const float* x        = (const float*)d_in[0];
    const float* base_w   = (const float*)d_in[1];
    const float* spline_w = (const float*)d_in[2];
    float* out = (float*)d_out;

    cudaFuncSetAttribute(k_gemm, cudaFuncAttributeMaxDynamicSharedMemorySize, SMEM_BYTES);

    k_prep<<<16384 + COUT, 256>>>(x, base_w, spline_w);
    dim3 grid(N_DIM / 128, M_DIM / 128);     // (4, 128) = 512 CTAs
    k_gemm<<<grid, 256, SMEM_BYTES>>>(out);
}